// round 13
// baseline (speedup 1.0000x reference)
#include <cuda_runtime.h>
#include <cuda_fp16.h>
#include <cstdint>

namespace {
constexpr int N_ROWS = 2048;
constexpr int DIM    = 256;
constexpr int NY     = 16384;          // T*Q
constexpr int NCOL   = NY + N_ROWS;    // 18432
constexpr int BM = 128, BN = 128;
constexpr int NCT   = NCOL / BN;       // 144 column tiles
constexpr int NCT_Y = NY / BN;         // 128 are y-tiles
constexpr int NRT   = N_ROWS / BM;     // 16 row tiles
constexpr int KC     = 64;             // f16 elems per smem stage (128B rows)
constexpr int NSTAGE = DIM / KC;       // 4
constexpr int NBUF   = 3;              // cp.async pipeline depth
constexpr int RSB    = 144;            // smem row stride bytes: 128 + 16 pad
constexpr int TB     = BM * RSB;       // 18432 B per tile buffer

constexpr uint32_t OFF_GJ  = 2 * NBUF * TB;       // 110592
constexpr uint32_t OFF_GI  = OFF_GJ + 512;
constexpr uint32_t SMEM_BYTES = OFF_GI + 1024;    // 112128 (2 CTA/SM)

constexpr float EXP_SCALE = 1.44269504088896340736f / 0.3f;  // log2(e)/TEMP
constexpr float INV_TEMP  = 1.0f / 0.3f;
}

__device__ __half g_xh[N_ROWS * DIM];   // 1 MB
__device__ __half g_yh[NY * DIM];       // 8 MB
__device__ float  g_rowacc[N_ROWS * 3];         // [row][{tot,pxy,pxx}]
__device__ float  g_tracksum[256 * 3];          // [track][{num,den,cnt}]
__device__ int    g_done;                       // tail arrival counter

__device__ __forceinline__ uint32_t smem_u32(const void* p) {
    uint32_t a;
    asm("{ .reg .u64 t; cvta.to.shared.u64 t, %1; cvt.u32.u64 %0, t; }" : "=r"(a) : "l"(p));
    return a;
}
__device__ __forceinline__ void cp16(uint32_t saddr, const void* g) {
    asm volatile("cp.async.cg.shared.global [%0], [%1], 16;" :: "r"(saddr), "l"(g));
}
__device__ __forceinline__ float fexp2(float z) {
    float r;
    asm("ex2.approx.f32 %0, %1;" : "=f"(r) : "f"(z));
    return r;
}
__device__ __forceinline__ void ldsm4(uint32_t* r, uint32_t addr) {
    asm volatile("ldmatrix.sync.aligned.m8n8.x4.shared.b16 {%0,%1,%2,%3}, [%4];"
        : "=r"(r[0]), "=r"(r[1]), "=r"(r[2]), "=r"(r[3]) : "r"(addr));
}
__device__ __forceinline__ void mma_f16(float* d, const uint32_t* a,
                                        uint32_t b0, uint32_t b1) {
    asm volatile(
        "mma.sync.aligned.m16n8k16.row.col.f32.f16.f16.f32 "
        "{%0,%1,%2,%3},{%4,%5,%6,%7},{%8,%9},{%0,%1,%2,%3};"
        : "+f"(d[0]), "+f"(d[1]), "+f"(d[2]), "+f"(d[3])
        : "r"(a[0]), "r"(a[1]), "r"(a[2]), "r"(a[3]), "r"(b0), "r"(b1));
}

// ---------------------------------------------------------------------------
// f32 -> f16 conversion (16 floats/thread) + zero all accumulators.
// ---------------------------------------------------------------------------
__global__ void __launch_bounds__(256)
convert(const float* __restrict__ x, const float* __restrict__ y) {
    const int bid = blockIdx.x;
    if (bid < 6) {
        int i = bid * 1024 + threadIdx.x * 4;
        if (i < N_ROWS * 3) {
            g_rowacc[i] = 0.f; g_rowacc[i + 1] = 0.f;
            g_rowacc[i + 2] = 0.f; g_rowacc[i + 3] = 0.f;
        }
    }
    if (bid == 6) {
        if (threadIdx.x < 256) {
            g_tracksum[threadIdx.x * 3 + 0] = 0.f;
            g_tracksum[threadIdx.x * 3 + 1] = 0.f;
            g_tracksum[threadIdx.x * 3 + 2] = 0.f;
        }
        if (threadIdx.x == 0) g_done = 0;
    }
    const float* src;
    __half* dst;
    size_t base;
    if (bid < 128) { src = x; dst = g_xh; base = (size_t)bid * 4096; }
    else           { src = y; dst = g_yh; base = (size_t)(bid - 128) * 4096; }
    const size_t i = base + (size_t)threadIdx.x * 16;
    float4 v0 = *(const float4*)(src + i);
    float4 v1 = *(const float4*)(src + i + 4);
    float4 v2 = *(const float4*)(src + i + 8);
    float4 v3 = *(const float4*)(src + i + 12);
    __half2 h0 = __floats2half2_rn(v0.x, v0.y);
    __half2 h1 = __floats2half2_rn(v0.z, v0.w);
    __half2 h2 = __floats2half2_rn(v1.x, v1.y);
    __half2 h3 = __floats2half2_rn(v1.z, v1.w);
    __half2 h4 = __floats2half2_rn(v2.x, v2.y);
    __half2 h5 = __floats2half2_rn(v2.z, v2.w);
    __half2 h6 = __floats2half2_rn(v3.x, v3.y);
    __half2 h7 = __floats2half2_rn(v3.z, v3.w);
    uint4 o0, o1;
    o0.x = *(uint32_t*)&h0; o0.y = *(uint32_t*)&h1;
    o0.z = *(uint32_t*)&h2; o0.w = *(uint32_t*)&h3;
    o1.x = *(uint32_t*)&h4; o1.y = *(uint32_t*)&h5;
    o1.z = *(uint32_t*)&h6; o1.w = *(uint32_t*)&h7;
    *(uint4*)(dst + i)     = o0;
    *(uint4*)(dst + i + 8) = o1;
}

// ---------------------------------------------------------------------------
// f16 mma.sync fused exp-GEMM; epilogue feeds per-row accumulators directly
// via L2 reduction atomics (no partial buffer, no smem combine).
// ---------------------------------------------------------------------------
__global__ void __launch_bounds__(256, 2)
gemm_tc(const __half* __restrict__ xh, const __half* __restrict__ yh,
        const int* __restrict__ trk) {
    extern __shared__ char smem[];
    const uint32_t sbase = smem_u32(smem);
    const int tid  = threadIdx.x;
    const int wid  = tid >> 5, lid = tid & 31;
    const int wm   = wid & 3, wn = wid >> 2;      // 4 x 2 warp grid
    const int quad = lid >> 2, qi = lid & 3;
    const int g    = lid >> 3, rr = lid & 7;      // ldmatrix lane groups
    const int ct = blockIdx.x;   // 0..143
    const int rt = blockIdx.y;   // 0..15

    int* sGJ = (int*)(smem + OFF_GJ);
    int* sGI = (int*)(smem + OFF_GI);
    if (tid < BM) {
        sGI[tid] = trk[rt * BM + tid];
        // y col group = global col % 256; tile base % 256 = (ct&1)*128
        sGJ[tid] = (ct < NCT_Y) ? ((ct & 1) * 128 + tid)
                                : trk[(ct - NCT_Y) * BN + tid];
    }

    const __half* Ab = xh + (size_t)rt * BM * DIM;
    const __half* Bb = (ct < NCT_Y) ? (yh + (size_t)ct * BN * DIM)
                                    : (xh + (size_t)(ct - NCT_Y) * BN * DIM);
    const int posoff = (ct < NCT_Y) ? 1 : 2;      // pxy vs pxx slot

    float acc[2][8][4];
#pragma unroll
    for (int fi = 0; fi < 2; ++fi)
#pragma unroll
        for (int nf = 0; nf < 8; ++nf)
#pragma unroll
            for (int r = 0; r < 4; ++r) acc[fi][nf][r] = 0.0f;

    // stage issue: tile = 128 rows x 8 chunks of 16B; 4 A + 4 B per thread
    auto issue_stage = [&](int s, int buf) {
#pragma unroll
        for (int i = 0; i < 4; ++i) {
            int id = tid + 256 * i;
            int r = id >> 3, q = id & 7;
            cp16(sbase + buf * TB + r * RSB + q * 16,
                 Ab + (size_t)r * DIM + s * KC + q * 8);
        }
#pragma unroll
        for (int i = 0; i < 4; ++i) {
            int id = tid + 256 * i;
            int r = id >> 3, q = id & 7;
            cp16(sbase + NBUF * TB + buf * TB + r * RSB + q * 16,
                 Bb + (size_t)r * DIM + s * KC + q * 8);
        }
        asm volatile("cp.async.commit_group;" ::: "memory");
    };

    issue_stage(0, 0);
    issue_stage(1, 1);

    // per-lane ldmatrix base offsets (within a tile buffer)
    const uint32_t aOff0 = (uint32_t)((wm * 32 + (g & 1) * 8 + rr) * RSB + (g >> 1) * 16);
    const uint32_t bOff0 = (uint32_t)((wn * 64 + (g >> 1) * 8 + rr) * RSB + (g & 1) * 16);

#pragma unroll
    for (int s = 0; s < NSTAGE; ++s) {
        const int buf = s % NBUF;
        if (s < NSTAGE - 1) {
            asm volatile("cp.async.wait_group 1;" ::: "memory");
        } else {
            asm volatile("cp.async.wait_group 0;" ::: "memory");
        }
        __syncthreads();   // stage s visible; all readers of buf (s+2)%3 done
        if (s + 2 < NSTAGE) issue_stage(s + 2, (s + 2) % NBUF);

        const uint32_t aBase = sbase + buf * TB + aOff0;
        const uint32_t bBase = sbase + NBUF * TB + buf * TB + bOff0;
#pragma unroll
        for (int k = 0; k < KC / 16; ++k) {       // 4 k16-steps (32B each)
            uint32_t a[2][4];
            ldsm4(a[0], aBase + k * 32);
            ldsm4(a[1], aBase + k * 32 + 16 * RSB);
            uint32_t bb[4][4];
#pragma unroll
            for (int p = 0; p < 4; ++p)
                ldsm4(bb[p], bBase + k * 32 + p * 16 * RSB);
#pragma unroll
            for (int nf = 0; nf < 8; ++nf) {
                uint32_t b0 = bb[nf >> 1][(nf & 1) * 2];
                uint32_t b1 = bb[nf >> 1][(nf & 1) * 2 + 1];
                mma_f16(acc[0][nf], a[0], b0, b1);
                mma_f16(acc[1][nf], a[1], b0, b1);
            }
        }
    }

    // ---- epilogue: exp + group-matched row sums -> L2 atomics per row.
#pragma unroll
    for (int fi = 0; fi < 2; ++fi) {
        const int r0 = wm * 32 + fi * 16 + quad;
        const int r1 = r0 + 8;
        const int gi0 = sGI[r0], gi1 = sGI[r1];
        float t0 = 0.f, p0 = 0.f, t1 = 0.f, p1 = 0.f;
#pragma unroll
        for (int nf = 0; nf < 8; ++nf) {
            const int c0 = wn * 64 + nf * 8 + 2 * qi;
            const int gj0 = sGJ[c0], gj1 = sGJ[c0 + 1];
            float e;
            e = fexp2(acc[fi][nf][0] * EXP_SCALE); t0 += e; if (gj0 == gi0) p0 += e;
            e = fexp2(acc[fi][nf][1] * EXP_SCALE); t0 += e; if (gj1 == gi0) p0 += e;
            e = fexp2(acc[fi][nf][2] * EXP_SCALE); t1 += e; if (gj0 == gi1) p1 += e;
            e = fexp2(acc[fi][nf][3] * EXP_SCALE); t1 += e; if (gj1 == gi1) p1 += e;
        }
#pragma unroll
        for (int o = 1; o <= 2; o <<= 1) {
            t0 += __shfl_xor_sync(0xffffffffu, t0, o);
            p0 += __shfl_xor_sync(0xffffffffu, p0, o);
            t1 += __shfl_xor_sync(0xffffffffu, t1, o);
            p1 += __shfl_xor_sync(0xffffffffu, p1, o);
        }
        if (qi == 0) {
            float* a0 = g_rowacc + (rt * BM + r0) * 3;
            float* a1 = g_rowacc + (rt * BM + r1) * 3;
            atomicAdd(a0, t0);
            atomicAdd(a0 + posoff, p0);
            atomicAdd(a1, t1);
            atomicAdd(a1 + posoff, p1);
        }
    }
}

// ---------------------------------------------------------------------------
// Fused tail: per-row num/den + diag exclusion -> track atomics; the last
// arriving block reduces the 256 tracks and writes the loss.
// ---------------------------------------------------------------------------
__global__ void __launch_bounds__(256)
tail(const float* __restrict__ x, const int* __restrict__ trk,
     float* __restrict__ out) {
    const int tid = threadIdx.x;
    const int w = tid >> 5, l = tid & 31;
    const int row = blockIdx.x * 8 + w;

    // diag = exp(|x_row|^2 / TEMP): 8 floats per lane
    const float4* xr = (const float4*)(x + (size_t)row * DIM);
    float sd = 0.f;
#pragma unroll
    for (int k = l; k < DIM / 4; k += 32) {
        float4 v = xr[k];
        sd += v.x * v.x + v.y * v.y + v.z * v.z + v.w * v.w;
    }
#pragma unroll
    for (int o = 16; o; o >>= 1) sd += __shfl_xor_sync(0xffffffffu, sd, o);

    if (l == 0) {
        float tot = g_rowacc[row * 3 + 0];
        float pxy = g_rowacc[row * 3 + 1];
        float pxx = g_rowacc[row * 3 + 2];
        float diag = __expf(sd * INV_TEMP);
        float num = pxy + 0.5f * (pxx - diag);
        float den = tot - pxy - pxx;
        float* a = g_tracksum + trk[row] * 3;
        atomicAdd(a + 0, num);
        atomicAdd(a + 1, den);
        atomicAdd(a + 2, 1.f);
    }

    // arrival: last block finalizes
    __syncthreads();
    __shared__ int islast;
    if (tid == 0) {
        __threadfence();
        islast = (atomicAdd(&g_done, 1) == (int)gridDim.x - 1);
    }
    __syncthreads();
    if (!islast) return;

    const int t = tid;
    float num = __ldcg(g_tracksum + t * 3 + 0);
    float den = __ldcg(g_tracksum + t * 3 + 1);
    float cnt = __ldcg(g_tracksum + t * 3 + 2);
    int present = (cnt > 0.f) ? 1 : 0;
    float loss = present ? -logf(num / (den + num)) : 0.f;
    float pres = (float)present;
#pragma unroll
    for (int o = 16; o; o >>= 1) {
        loss += __shfl_xor_sync(0xffffffffu, loss, o);
        pres += __shfl_xor_sync(0xffffffffu, pres, o);
    }
    __shared__ float sl[8], sp[8];
    if (l == 0) { sl[w] = loss; sp[w] = pres; }
    __syncthreads();
    if (t == 0) {
        float L = 0.f, P = 0.f;
#pragma unroll
        for (int i = 0; i < 8; ++i) { L += sl[i]; P += sp[i]; }
        out[0] = L / P;
    }
}

// ---------------------------------------------------------------------------
extern "C" void kernel_launch(void* const* d_in, const int* in_sizes, int n_in,
                              void* d_out, int out_size) {
    const float* x   = (const float*)d_in[0];
    const int*   trk = (const int*)  d_in[1];
    const float* y   = (const float*)d_in[2];

    static __half* xh_p = nullptr;
    static __half* yh_p = nullptr;
    if (!xh_p) {
        cudaGetSymbolAddress((void**)&xh_p, g_xh);
        cudaGetSymbolAddress((void**)&yh_p, g_yh);
        cudaFuncSetAttribute(gemm_tc, cudaFuncAttributeMaxDynamicSharedMemorySize,
                             (int)SMEM_BYTES);
    }

    convert<<<128 + NY * DIM / 4096, 256>>>(x, y);
    dim3 grid(NCT, NRT);
    gemm_tc<<<grid, 256, SMEM_BYTES>>>(xh_p, yh_p, trk);
    tail<<<N_ROWS / 8, 256>>>(x, trk, (float*)d_out);
}

// round 14
// speedup vs baseline: 1.1335x; 1.1335x over previous
#include <cuda_runtime.h>
#include <cuda_fp16.h>
#include <cstdint>

namespace {
constexpr int N_ROWS = 2048;
constexpr int DIM    = 256;
constexpr int NY     = 16384;          // T*Q
constexpr int NCOL   = NY + N_ROWS;    // 18432
constexpr int BM = 128, BN = 128;
constexpr int NCT   = NCOL / BN;       // 144 column tiles
constexpr int NCT_Y = NY / BN;         // 128 are y-tiles
constexpr int NRT   = N_ROWS / BM;     // 16 row tiles
constexpr int KC     = 64;             // f16 elems per smem stage (128B rows)
constexpr int NSTAGE = DIM / KC;       // 4
constexpr int NBUF   = 3;              // cp.async pipeline depth
constexpr int RSB    = 144;            // smem row stride bytes: 128 + 16 pad
constexpr int TB     = BM * RSB;       // 18432 B per tile buffer

constexpr uint32_t OFF_B   = NBUF * TB;           // B buffers after A buffers
constexpr uint32_t OFF_GJ  = 2 * NBUF * TB;       // 110592
constexpr uint32_t OFF_GI  = OFF_GJ + 512;
constexpr uint32_t OFF_CMB = OFF_GI + 512;
constexpr uint32_t SMEM_BYTES = OFF_CMB + 1024;   // 112640 (2 CTA/SM)

constexpr float EXP_SCALE = 1.44269504088896340736f / 0.3f;  // log2(e)/TEMP
constexpr float INV_TEMP  = 1.0f / 0.3f;
}

__device__ __half g_xh[N_ROWS * DIM];   // 1 MB
__device__ __half g_yh[NY * DIM];       // 8 MB
__device__ float  g_partial[N_ROWS * NCT * 2];  // [row][ct][{tot,pos}]
__device__ float  g_tracksum[256 * 3];          // [track][{num,den,cnt}]
__device__ int    g_done;                       // tail arrival counter

__device__ __forceinline__ uint32_t smem_u32(const void* p) {
    uint32_t a;
    asm("{ .reg .u64 t; cvta.to.shared.u64 t, %1; cvt.u32.u64 %0, t; }" : "=r"(a) : "l"(p));
    return a;
}
__device__ __forceinline__ void cp16(uint32_t saddr, const void* g) {
    asm volatile("cp.async.cg.shared.global [%0], [%1], 16;" :: "r"(saddr), "l"(g));
}
__device__ __forceinline__ float fexp2(float z) {
    float r;
    asm("ex2.approx.f32 %0, %1;" : "=f"(r) : "f"(z));
    return r;
}
__device__ __forceinline__ void ldsm4(uint32_t* r, uint32_t addr) {
    asm volatile("ldmatrix.sync.aligned.m8n8.x4.shared.b16 {%0,%1,%2,%3}, [%4];"
        : "=r"(r[0]), "=r"(r[1]), "=r"(r[2]), "=r"(r[3]) : "r"(addr));
}
__device__ __forceinline__ void mma_f16(float* d, const uint32_t* a,
                                        uint32_t b0, uint32_t b1) {
    asm volatile(
        "mma.sync.aligned.m16n8k16.row.col.f32.f16.f16.f32 "
        "{%0,%1,%2,%3},{%4,%5,%6,%7},{%8,%9},{%0,%1,%2,%3};"
        : "+f"(d[0]), "+f"(d[1]), "+f"(d[2]), "+f"(d[3])
        : "r"(a[0]), "r"(a[1]), "r"(a[2]), "r"(a[3]), "r"(b0), "r"(b1));
}

// ---------------------------------------------------------------------------
// f32 -> f16 conversion of x and y (8 floats/thread) + zero accumulators.
// ---------------------------------------------------------------------------
__global__ void __launch_bounds__(256)
convert(const float* __restrict__ x, const float* __restrict__ y) {
    const int bid = blockIdx.x;
    if (bid == 0) {
        if (threadIdx.x < 256) {
            g_tracksum[threadIdx.x * 3 + 0] = 0.f;
            g_tracksum[threadIdx.x * 3 + 1] = 0.f;
            g_tracksum[threadIdx.x * 3 + 2] = 0.f;
        }
        if (threadIdx.x == 0) g_done = 0;
    }
    const float* src;
    __half* dst;
    size_t base;
    if (bid < 256) { src = x; dst = g_xh; base = (size_t)bid * 2048; }
    else           { src = y; dst = g_yh; base = (size_t)(bid - 256) * 2048; }
    const size_t i = base + (size_t)threadIdx.x * 8;
    float4 v0 = *(const float4*)(src + i);
    float4 v1 = *(const float4*)(src + i + 4);
    __half2 h0 = __floats2half2_rn(v0.x, v0.y);
    __half2 h1 = __floats2half2_rn(v0.z, v0.w);
    __half2 h2 = __floats2half2_rn(v1.x, v1.y);
    __half2 h3 = __floats2half2_rn(v1.z, v1.w);
    uint4 o;
    o.x = *(uint32_t*)&h0; o.y = *(uint32_t*)&h1;
    o.z = *(uint32_t*)&h2; o.w = *(uint32_t*)&h3;
    *(uint4*)(dst + i) = o;
}

// ---------------------------------------------------------------------------
// f16 mma.sync fused exp-GEMM; ldmatrix fragment loads; 3-deep cp.async pipe.
// (identical to the 67.3us R10 version)
// ---------------------------------------------------------------------------
__global__ void __launch_bounds__(256, 2)
gemm_tc(const __half* __restrict__ xh, const __half* __restrict__ yh,
        const int* __restrict__ trk) {
    extern __shared__ char smem[];
    const uint32_t sbase = smem_u32(smem);
    const int tid  = threadIdx.x;
    const int wid  = tid >> 5, lid = tid & 31;
    const int wm   = wid & 3, wn = wid >> 2;      // 4 x 2 warp grid
    const int quad = lid >> 2, qi = lid & 3;
    const int g    = lid >> 3, rr = lid & 7;      // ldmatrix lane groups
    const int ct = blockIdx.x;   // 0..143
    const int rt = blockIdx.y;   // 0..15

    int* sGJ = (int*)(smem + OFF_GJ);
    int* sGI = (int*)(smem + OFF_GI);
    if (tid < BM) {
        sGI[tid] = trk[rt * BM + tid];
        // y col group = global col % 256; tile base % 256 = (ct&1)*128
        sGJ[tid] = (ct < NCT_Y) ? ((ct & 1) * 128 + tid)
                                : trk[(ct - NCT_Y) * BN + tid];
    }

    const __half* Ab = xh + (size_t)rt * BM * DIM;
    const __half* Bb = (ct < NCT_Y) ? (yh + (size_t)ct * BN * DIM)
                                    : (xh + (size_t)(ct - NCT_Y) * BN * DIM);

    float acc[2][8][4];
#pragma unroll
    for (int fi = 0; fi < 2; ++fi)
#pragma unroll
        for (int nf = 0; nf < 8; ++nf)
#pragma unroll
            for (int r = 0; r < 4; ++r) acc[fi][nf][r] = 0.0f;

    auto issue_stage = [&](int s, int buf) {
#pragma unroll
        for (int i = 0; i < 4; ++i) {
            int id = tid + 256 * i;
            int r = id >> 3, q = id & 7;
            cp16(sbase + buf * TB + r * RSB + q * 16,
                 Ab + (size_t)r * DIM + s * KC + q * 8);
        }
#pragma unroll
        for (int i = 0; i < 4; ++i) {
            int id = tid + 256 * i;
            int r = id >> 3, q = id & 7;
            cp16(sbase + OFF_B + buf * TB + r * RSB + q * 16,
                 Bb + (size_t)r * DIM + s * KC + q * 8);
        }
        asm volatile("cp.async.commit_group;" ::: "memory");
    };

    issue_stage(0, 0);
    issue_stage(1, 1);

    const uint32_t aOff0 = (uint32_t)((wm * 32 + (g & 1) * 8 + rr) * RSB + (g >> 1) * 16);
    const uint32_t bOff0 = (uint32_t)((wn * 64 + (g >> 1) * 8 + rr) * RSB + (g & 1) * 16);

#pragma unroll
    for (int s = 0; s < NSTAGE; ++s) {
        const int buf = s % NBUF;
        if (s < NSTAGE - 1) {
            asm volatile("cp.async.wait_group 1;" ::: "memory");
        } else {
            asm volatile("cp.async.wait_group 0;" ::: "memory");
        }
        __syncthreads();
        if (s + 2 < NSTAGE) issue_stage(s + 2, (s + 2) % NBUF);

        const uint32_t aBase = sbase + buf * TB + aOff0;
        const uint32_t bBase = sbase + OFF_B + buf * TB + bOff0;
#pragma unroll
        for (int k = 0; k < KC / 16; ++k) {
            uint32_t a[2][4];
            ldsm4(a[0], aBase + k * 32);
            ldsm4(a[1], aBase + k * 32 + 16 * RSB);
            uint32_t bb[4][4];
#pragma unroll
            for (int p = 0; p < 4; ++p)
                ldsm4(bb[p], bBase + k * 32 + p * 16 * RSB);
#pragma unroll
            for (int nf = 0; nf < 8; ++nf) {
                uint32_t b0 = bb[nf >> 1][(nf & 1) * 2];
                uint32_t b1 = bb[nf >> 1][(nf & 1) * 2 + 1];
                mma_f16(acc[0][nf], a[0], b0, b1);
                mma_f16(acc[1][nf], a[1], b0, b1);
            }
        }
    }

    // ---- epilogue: exp + group-matched row sums, deterministic STG partials.
    __syncthreads();
    float2* CMB = (float2*)(smem + OFF_CMB);
#pragma unroll
    for (int fi = 0; fi < 2; ++fi) {
        const int r0 = wm * 32 + fi * 16 + quad;
        const int r1 = r0 + 8;
        const int gi0 = sGI[r0], gi1 = sGI[r1];
        float t0 = 0.f, p0 = 0.f, t1 = 0.f, p1 = 0.f;
#pragma unroll
        for (int nf = 0; nf < 8; ++nf) {
            const int c0 = wn * 64 + nf * 8 + 2 * qi;
            const int gj0 = sGJ[c0], gj1 = sGJ[c0 + 1];
            float e;
            e = fexp2(acc[fi][nf][0] * EXP_SCALE); t0 += e; if (gj0 == gi0) p0 += e;
            e = fexp2(acc[fi][nf][1] * EXP_SCALE); t0 += e; if (gj1 == gi0) p0 += e;
            e = fexp2(acc[fi][nf][2] * EXP_SCALE); t1 += e; if (gj0 == gi1) p1 += e;
            e = fexp2(acc[fi][nf][3] * EXP_SCALE); t1 += e; if (gj1 == gi1) p1 += e;
        }
#pragma unroll
        for (int o = 1; o <= 2; o <<= 1) {
            t0 += __shfl_xor_sync(0xffffffffu, t0, o);
            p0 += __shfl_xor_sync(0xffffffffu, p0, o);
            t1 += __shfl_xor_sync(0xffffffffu, t1, o);
            p1 += __shfl_xor_sync(0xffffffffu, p1, o);
        }
        if (qi == 0 && wn == 1) {
            CMB[r0] = make_float2(t0, p0);
            CMB[r1] = make_float2(t1, p1);
        }
        if (fi == 0) { acc[0][0][0] = t0; acc[0][0][1] = p0; acc[0][0][2] = t1; acc[0][0][3] = p1; }
        else         { acc[1][0][0] = t0; acc[1][0][1] = p0; acc[1][0][2] = t1; acc[1][0][3] = p1; }
    }
    __syncthreads();
    if (qi == 0 && wn == 0) {
#pragma unroll
        for (int fi = 0; fi < 2; ++fi) {
            const int r0 = wm * 32 + fi * 16 + quad;
            const int r1 = r0 + 8;
            float2 o0 = CMB[r0], o1 = CMB[r1];
            float* g0 = g_partial + (((size_t)(rt * BM + r0)) * NCT + ct) * 2;
            float* g1 = g_partial + (((size_t)(rt * BM + r1)) * NCT + ct) * 2;
            g0[0] = acc[fi][0][0] + o0.x;
            g0[1] = acc[fi][0][1] + o0.y;
            g1[0] = acc[fi][0][2] + o1.x;
            g1[1] = acc[fi][0][3] + o1.y;
        }
    }
}

// ---------------------------------------------------------------------------
// Fused tail: warp-per-row reduction over tiles + diag exclusion -> track
// atomics; the last arriving block reduces 256 tracks and writes the loss.
// ---------------------------------------------------------------------------
__global__ void __launch_bounds__(256)
tail(const float* __restrict__ x, const int* __restrict__ trk,
     float* __restrict__ out) {
    const int tid = threadIdx.x;
    const int w = tid >> 5, l = tid & 31;
    const int row = blockIdx.x * 8 + w;

    float tot = 0.f, pxy = 0.f, pxx = 0.f;
    const float2* p = (const float2*)(g_partial + (size_t)row * NCT * 2);
#pragma unroll
    for (int tv = l; tv < NCT; tv += 32) {
        float2 v = p[tv];
        tot += v.x;
        if (tv < NCT_Y) pxy += v.y; else pxx += v.y;
    }
    const float4* xr = (const float4*)(x + (size_t)row * DIM);
    float sd = 0.f;
#pragma unroll
    for (int k = l; k < DIM / 4; k += 32) {
        float4 v = xr[k];
        sd += v.x * v.x + v.y * v.y + v.z * v.z + v.w * v.w;
    }
#pragma unroll
    for (int o = 16; o; o >>= 1) {
        tot += __shfl_xor_sync(0xffffffffu, tot, o);
        pxy += __shfl_xor_sync(0xffffffffu, pxy, o);
        pxx += __shfl_xor_sync(0xffffffffu, pxx, o);
        sd  += __shfl_xor_sync(0xffffffffu, sd,  o);
    }
    if (l == 0) {
        float diag = __expf(sd * INV_TEMP);
        float num = pxy + 0.5f * (pxx - diag);
        float den = tot - pxy - pxx;
        float* a = g_tracksum + trk[row] * 3;
        atomicAdd(a + 0, num);
        atomicAdd(a + 1, den);
        atomicAdd(a + 2, 1.f);
    }

    __syncthreads();
    __shared__ int islast;
    if (tid == 0) {
        __threadfence();
        islast = (atomicAdd(&g_done, 1) == (int)gridDim.x - 1);
    }
    __syncthreads();
    if (!islast) return;

    const int t = tid;
    float num = __ldcg(g_tracksum + t * 3 + 0);
    float den = __ldcg(g_tracksum + t * 3 + 1);
    float cnt = __ldcg(g_tracksum + t * 3 + 2);
    int present = (cnt > 0.f) ? 1 : 0;
    float loss = present ? -logf(num / (den + num)) : 0.f;
    float pres = (float)present;
#pragma unroll
    for (int o = 16; o; o >>= 1) {
        loss += __shfl_xor_sync(0xffffffffu, loss, o);
        pres += __shfl_xor_sync(0xffffffffu, pres, o);
    }
    __shared__ float sl[8], sp[8];
    if (l == 0) { sl[w] = loss; sp[w] = pres; }
    __syncthreads();
    if (t == 0) {
        float L = 0.f, P = 0.f;
#pragma unroll
        for (int i = 0; i < 8; ++i) { L += sl[i]; P += sp[i]; }
        out[0] = L / P;
    }
}

// ---------------------------------------------------------------------------
extern "C" void kernel_launch(void* const* d_in, const int* in_sizes, int n_in,
                              void* d_out, int out_size) {
    const float* x   = (const float*)d_in[0];
    const int*   trk = (const int*)  d_in[1];
    const float* y   = (const float*)d_in[2];

    static __half* xh_p = nullptr;
    static __half* yh_p = nullptr;
    if (!xh_p) {
        cudaGetSymbolAddress((void**)&xh_p, g_xh);
        cudaGetSymbolAddress((void**)&yh_p, g_yh);
        cudaFuncSetAttribute(gemm_tc, cudaFuncAttributeMaxDynamicSharedMemorySize,
                             (int)SMEM_BYTES);
    }

    convert<<<256 + NY * DIM / 2048, 256>>>(x, y);
    dim3 grid(NCT, NRT);
    gemm_tc<<<grid, 256, SMEM_BYTES>>>(xh_p, yh_p, trk);
    tail<<<N_ROWS / 8, 256>>>(x, trk, (float*)d_out);
}